// round 6
// baseline (speedup 1.0000x reference)
#include <cuda_runtime.h>
#include <cstdint>

#define BATCH 32
#define IMH 1024
#define IMW 1024
#define NBOX 96
#define WARPS 8
#define NTHREADS 256
#define STAGE_ROWS 8                         // one row per warp per stage
#define NITER 8                              // stages per block
#define ROWS_PER_BLOCK (STAGE_ROWS * NITER)  // 64
#define GRID (BATCH * IMH / ROWS_PER_BLOCK)  // 512
#define STAGE_FLOATS (STAGE_ROWS * IMW)      // 8192
#define STAGE_BYTES (STAGE_FLOATS * 4)       // 32 KB
#define NSTAGE 2

// Per-(batch,box) rectangle sums. Zero-initialized at module load; the last
// block resets it after reading so every graph replay starts clean.
__device__ float    g_boxsum[BATCH * NBOX];
__device__ unsigned g_done;

__device__ __forceinline__ uint32_t smem_u32(const void* p) {
    return (uint32_t)__cvta_generic_to_shared(p);
}

__device__ __forceinline__ void mbar_init(uint32_t addr, uint32_t cnt) {
    asm volatile("mbarrier.init.shared.b64 [%0], %1;" :: "r"(addr), "r"(cnt) : "memory");
}
__device__ __forceinline__ void mbar_expect_tx(uint32_t addr, uint32_t bytes) {
    asm volatile("mbarrier.arrive.expect_tx.shared.b64 _, [%0], %1;"
                 :: "r"(addr), "r"(bytes) : "memory");
}
__device__ __forceinline__ void mbar_wait(uint32_t addr, uint32_t parity) {
    uint32_t done = 0;
    while (!done) {
        asm volatile(
            "{\n\t.reg .pred p;\n\t"
            "mbarrier.try_wait.parity.acquire.cta.shared::cta.b64 p, [%1], %2;\n\t"
            "selp.b32 %0, 1, 0, p;\n\t}"
            : "=r"(done) : "r"(addr), "r"(parity) : "memory");
    }
}
__device__ __forceinline__ void bulk_g2s(uint32_t dst_smem, const void* src,
                                         uint32_t bytes, uint32_t mbar) {
    asm volatile(
        "cp.async.bulk.shared::cluster.global.mbarrier::complete_tx::bytes "
        "[%0], [%1], %2, [%3];"
        :: "r"(dst_smem), "l"(src), "r"(bytes), "r"(mbar) : "memory");
}
__device__ __forceinline__ void fence_async_shared() {
    asm volatile("fence.proxy.async.shared::cta;" ::: "memory");
}

__global__ __launch_bounds__(NTHREADS)
void fused_kernel(const float* __restrict__ img, const int* __restrict__ bb,
                  float* __restrict__ out) {
    extern __shared__ __align__(16) unsigned char smem_raw[];
    float*    buf   = (float*)smem_raw;                                   // 2 × 32 KB
    int4*     sbox  = (int4*)(smem_raw + NSTAGE * STAGE_BYTES);           // 1.5 KB
    uint64_t* mbarp = (uint64_t*)(smem_raw + NSTAGE * STAGE_BYTES + NBOX * 16);

    const int t    = threadIdx.x;
    const int lane = t & 31;
    const int w    = t >> 5;
    const int blocksPerBatch = IMH / ROWS_PER_BLOCK;                      // 16
    const int b       = blockIdx.x / blocksPerBatch;
    const int rowBase = (blockIdx.x % blocksPerBatch) * ROWS_PER_BLOCK;

    const uint32_t mbar0 = smem_u32(mbarp);
    const uint32_t mbar1 = mbar0 + 8;
    const uint32_t bufsa = smem_u32(buf);

    if (t < NBOX) sbox[t] = ((const int4*)bb)[b * NBOX + t];
    if (t == 0) {
        mbar_init(mbar0, 1);
        mbar_init(mbar1, 1);
        fence_async_shared();
    }
    __syncthreads();

    const float* gsrc = img + (size_t)b * IMH * IMW + (size_t)rowBase * IMW;

    // Prologue: fill both stages.
    if (t == 0) {
        mbar_expect_tx(mbar0, STAGE_BYTES);
        bulk_g2s(bufsa, gsrc, STAGE_BYTES, mbar0);
        mbar_expect_tx(mbar1, STAGE_BYTES);
        bulk_g2s(bufsa + STAGE_BYTES, gsrc + STAGE_FLOATS, STAGE_BYTES, mbar1);
    }

    // Per-lane box state (3 boxes per lane).
    int   bx1[3], bx2[3], by1[3], by2[3];
    bool  bval[3];
    float bacc[3];
#pragma unroll
    for (int k = 0; k < 3; k++) {
        int4 box = sbox[lane + 32 * k];
        bx1[k] = min(max(box.x, 0), IMW);
        by1[k] = min(max(box.y, 0), IMW);
        bx2[k] = min(max(box.z, 0), IMW);
        by2[k] = min(max(box.w, 0), IMW);
        bval[k] = (bx2[k] > bx1[k]) && (by2[k] > by1[k]);
        bacc[k] = 0.0f;
    }

    for (int i = 0; i < NITER; ++i) {
        const int s = i & 1;
        mbar_wait(s ? mbar1 : mbar0, (i >> 1) & 1);

        float* rowp = buf + s * STAGE_FLOATS + w * IMW;   // this warp's row
        const int row = rowBase + i * STAGE_ROWS + w;

        // Load row into registers (conflict-free LDS.128).
        float4 v[8];
#pragma unroll
        for (int j = 0; j < 8; j++)
            v[j] = *(const float4*)(rowp + 128 * j + 4 * lane);

        // Segment sums + eight warp scans chained through a scalar base.
        float excl[8];
        float base = 0.0f;
#pragma unroll
        for (int j = 0; j < 8; j++) {
            float sj = (v[j].x + v[j].y) + (v[j].z + v[j].w);
            float sc = sj;
#pragma unroll
            for (int o = 1; o < 32; o <<= 1) {
                float u = __shfl_up_sync(0xffffffffu, sc, o);
                if (lane >= o) sc += u;
            }
            excl[j] = (sc - sj) + base;
            base += __shfl_sync(0xffffffffu, sc, 31);
        }

        // Write exclusive prefixes back IN PLACE (raw data already consumed).
#pragma unroll
        for (int j = 0; j < 8; j++) {
            float4 p;
            p.x = excl[j];
            p.y = p.x + v[j].x;
            p.z = p.y + v[j].y;
            p.w = p.z + v[j].z;
            *(float4*)(rowp + 128 * j + 4 * lane) = p;
        }
        __syncwarp();

        // Serve this row for all 96 boxes (3 per lane). prefix(1024) == base.
#pragma unroll
        for (int k = 0; k < 3; k++) {
            if (bval[k] && by1[k] <= row && row < by2[k]) {
                float right = (bx2[k] == IMW) ? base : rowp[bx2[k]];
                bacc[k] += right - rowp[bx1[k]];
            }
        }

        __syncthreads();   // all warps done with this stage buffer

        // Re-arm this stage for iteration i+2.
        if (t == 0 && i + 2 < NITER) {
            fence_async_shared();   // order generic STS before async-proxy overwrite
            const uint32_t mb = s ? mbar1 : mbar0;
            mbar_expect_tx(mb, STAGE_BYTES);
            bulk_g2s(bufsa + s * STAGE_BYTES,
                     gsrc + (size_t)(i + 2) * STAGE_FLOATS, STAGE_BYTES, mb);
        }
    }

#pragma unroll
    for (int k = 0; k < 3; k++)
        if (bval[k] && bacc[k] != 0.0f)
            atomicAdd(&g_boxsum[b * NBOX + lane + 32 * k], bacc[k]);

    // ---- last-block epilogue: loss + state reset ----
    __shared__ unsigned lastflag;
    __threadfence();
    if (t == 0) {
        unsigned vdone = atomicAdd(&g_done, 1u);
        lastflag = (vdone == (unsigned)(gridDim.x - 1));
    }
    __syncthreads();

    if (lastflag) {
        float sum = 0.0f;
#pragma unroll 4
        for (int i = t; i < BATCH * NBOX; i += NTHREADS) {
            float sv = __ldcg(&g_boxsum[i]);
            g_boxsum[i] = 0.0f;                 // reset for next replay
            float d = 1.0f - sv;                // invalid boxes stayed 0 -> contribute 1
            sum += (d > 0.0f) ? d : 0.0f;
        }
        __shared__ float red[WARPS];
#pragma unroll
        for (int o = 16; o; o >>= 1) sum += __shfl_down_sync(0xffffffffu, sum, o);
        if (lane == 0) red[w] = sum;
        __syncthreads();
        if (w == 0) {
            sum = (lane < WARPS) ? red[lane] : 0.0f;
#pragma unroll
            for (int o = 16; o; o >>= 1) sum += __shfl_down_sync(0xffffffffu, sum, o);
            if (lane == 0) {
                *out = sum;
                g_done = 0u;                    // reset counter for next replay
            }
        }
    }
}

extern "C" void kernel_launch(void* const* d_in, const int* in_sizes, int n_in,
                              void* d_out, int out_size) {
    const float* img = (const float*)d_in[0];   // (32,1,1024,1024) fp32
    const int*   bb  = (const int*)d_in[1];     // (32,96,4) int32
    float* out = (float*)d_out;

    const int smem = NSTAGE * STAGE_BYTES + NBOX * 16 + 64;
    cudaFuncSetAttribute(fused_kernel, cudaFuncAttributeMaxDynamicSharedMemorySize, smem);
    fused_kernel<<<GRID, NTHREADS, smem>>>(img, bb, out);
}

// round 7
// speedup vs baseline: 1.0589x; 1.0589x over previous
#include <cuda_runtime.h>
#include <cstdint>

#define BATCH 32
#define IMH 1024
#define IMW 1024
#define NBOX 96
#define WARPS 4
#define NTHREADS 128
#define RPW 8                                  // rows per warp
#define ROWS_PER_BLOCK (WARPS * RPW)           // 32
#define GRID (BATCH * IMH / ROWS_PER_BLOCK)    // 1024
#define DEPTH 3                                // cp.async ring depth (rows)
#define ROW_FLOATS IMW
#define ROW_BYTES (IMW * 4)                    // 4 KB

// Per-(batch,box) rectangle sums. Zero-initialized at module load; the last
// block resets it after reading so every graph replay starts clean.
__device__ float    g_boxsum[BATCH * NBOX];
__device__ unsigned g_done;

__device__ __forceinline__ uint32_t smem_u32(const void* p) {
    return (uint32_t)__cvta_generic_to_shared(p);
}
__device__ __forceinline__ void cpasync16(uint32_t dst, const void* src) {
    asm volatile("cp.async.cg.shared.global [%0], [%1], 16;"
                 :: "r"(dst), "l"(src) : "memory");
}
__device__ __forceinline__ void cp_commit() {
    asm volatile("cp.async.commit_group;" ::: "memory");
}
template <int N>
__device__ __forceinline__ void cp_wait() {
    asm volatile("cp.async.wait_group %0;" :: "n"(N) : "memory");
}

__global__ __launch_bounds__(NTHREADS)
void fused_kernel(const float* __restrict__ img, const int* __restrict__ bb,
                  float* __restrict__ out) {
    extern __shared__ __align__(16) float smem[];
    // layout: [WARPS*DEPTH row slots of 1024 floats][96 int4 boxes]
    int4* sbox = (int4*)(smem + WARPS * DEPTH * ROW_FLOATS);

    const int t    = threadIdx.x;
    const int lane = t & 31;
    const int w    = t >> 5;
    const int blocksPerBatch = IMH / ROWS_PER_BLOCK;     // 32
    const int b        = blockIdx.x / blocksPerBatch;
    const int rowStart = (blockIdx.x % blocksPerBatch) * ROWS_PER_BLOCK + w * RPW;

    if (t < NBOX) sbox[t] = ((const int4*)bb)[b * NBOX + t];
    __syncthreads();   // only block-wide sync in the kernel body

    // Per-lane box state (3 boxes per lane).
    int   bx1[3], bx2[3], by1[3], by2[3];
    bool  bval[3];
    float bacc[3];
#pragma unroll
    for (int k = 0; k < 3; k++) {
        int4 box = sbox[lane + 32 * k];
        bx1[k] = min(max(box.x, 0), IMW);
        by1[k] = min(max(box.y, 0), IMW);
        bx2[k] = min(max(box.z, 0), IMW);
        by2[k] = min(max(box.w, 0), IMW);
        bval[k] = (bx2[k] > bx1[k]) && (by2[k] > by1[k]);
        bacc[k] = 0.0f;
    }

    float* slots = smem + w * DEPTH * ROW_FLOATS;        // this warp's 3 slots
    const float* gwarp = img + (size_t)b * IMH * IMW + (size_t)rowStart * IMW;

    // Prologue: prefetch rows 0..2, one commit group per row.
#pragma unroll
    for (int p = 0; p < DEPTH; p++) {
        const float* src = gwarp + (size_t)p * ROW_FLOATS;
        uint32_t dst = smem_u32(slots + p * ROW_FLOATS);
#pragma unroll
        for (int op = 0; op < 8; op++)
            cpasync16(dst + op * 512 + lane * 16, src + op * 128 + lane * 4);
        cp_commit();
    }

    for (int r = 0; r < RPW; ++r) {
        // Group algebra: before this wait, committed groups = 3 + r (one per
        // prologue row + one per prior iteration, some possibly empty).
        // wait<2> ==> groups 0..r complete ==> row r resident.
        cp_wait<2>();

        float* rowp = slots + (r % DEPTH) * ROW_FLOATS;
        const int row = rowStart + r;

        // Each lane reads exactly the bytes its own cp.async wrote -> no sync.
        float4 v[8];
#pragma unroll
        for (int j = 0; j < 8; j++)
            v[j] = *(const float4*)(rowp + 128 * j + 4 * lane);

        // Segment sums + eight warp scans chained through a scalar base.
        float excl[8];
        float base = 0.0f;
#pragma unroll
        for (int j = 0; j < 8; j++) {
            float sj = (v[j].x + v[j].y) + (v[j].z + v[j].w);
            float sc = sj;
#pragma unroll
            for (int o = 1; o < 32; o <<= 1) {
                float u = __shfl_up_sync(0xffffffffu, sc, o);
                if (lane >= o) sc += u;
            }
            excl[j] = (sc - sj) + base;
            base += __shfl_sync(0xffffffffu, sc, 31);
        }

        // Exclusive prefixes written in place (raw data consumed).
#pragma unroll
        for (int j = 0; j < 8; j++) {
            float4 p;
            p.x = excl[j];
            p.y = p.x + v[j].x;
            p.z = p.y + v[j].y;
            p.w = p.z + v[j].z;
            *(float4*)(rowp + 128 * j + 4 * lane) = p;
        }
        __syncwarp();

        // Serve this row for all 96 boxes (3 per lane). prefix(1024) == base.
#pragma unroll
        for (int k = 0; k < 3; k++) {
            if (bval[k] && by1[k] <= row && row < by2[k]) {
                float right = (bx2[k] == IMW) ? base : rowp[bx2[k]];
                bacc[k] += right - rowp[bx1[k]];
            }
        }
        __syncwarp();   // all lanes done with this slot

        // Refill the just-freed slot with row r+3; commit unconditionally so
        // the committed-group count stays 3 + r + 1.
        if (r + DEPTH < RPW) {
            const float* src = gwarp + (size_t)(r + DEPTH) * ROW_FLOATS;
            uint32_t dst = smem_u32(rowp);
#pragma unroll
            for (int op = 0; op < 8; op++)
                cpasync16(dst + op * 512 + lane * 16, src + op * 128 + lane * 4);
        }
        cp_commit();
    }

#pragma unroll
    for (int k = 0; k < 3; k++)
        if (bval[k] && bacc[k] != 0.0f)
            atomicAdd(&g_boxsum[b * NBOX + lane + 32 * k], bacc[k]);

    // ---- last-block epilogue: loss + state reset ----
    __shared__ unsigned lastflag;
    __threadfence();
    if (t == 0) {
        unsigned vdone = atomicAdd(&g_done, 1u);
        lastflag = (vdone == (unsigned)(gridDim.x - 1));
    }
    __syncthreads();

    if (lastflag) {
        float sum = 0.0f;
#pragma unroll 4
        for (int i = t; i < BATCH * NBOX; i += NTHREADS) {
            float sv = __ldcg(&g_boxsum[i]);
            g_boxsum[i] = 0.0f;                 // reset for next replay
            float d = 1.0f - sv;                // invalid boxes stayed 0 -> contribute 1
            sum += (d > 0.0f) ? d : 0.0f;
        }
        __shared__ float red[WARPS];
#pragma unroll
        for (int o = 16; o; o >>= 1) sum += __shfl_down_sync(0xffffffffu, sum, o);
        if (lane == 0) red[w] = sum;
        __syncthreads();
        if (w == 0) {
            sum = (lane < WARPS) ? red[lane] : 0.0f;
#pragma unroll
            for (int o = 16; o; o >>= 1) sum += __shfl_down_sync(0xffffffffu, sum, o);
            if (lane == 0) {
                *out = sum;
                g_done = 0u;                    // reset counter for next replay
            }
        }
    }
}

extern "C" void kernel_launch(void* const* d_in, const int* in_sizes, int n_in,
                              void* d_out, int out_size) {
    const float* img = (const float*)d_in[0];   // (32,1,1024,1024) fp32
    const int*   bb  = (const int*)d_in[1];     // (32,96,4) int32
    float* out = (float*)d_out;

    const int smem = (WARPS * DEPTH * ROW_FLOATS) * 4 + NBOX * 16 + 64;
    cudaFuncSetAttribute(fused_kernel, cudaFuncAttributeMaxDynamicSharedMemorySize, smem);
    fused_kernel<<<GRID, NTHREADS, smem>>>(img, bb, out);
}